// round 1
// baseline (speedup 1.0000x reference)
#include <cuda_runtime.h>
#include <math.h>

// MaskedNorm: B=8, T=4096, C=1024 fp32.
// y: [B,T,C], mask: [B,1,T] (flattened B*T ints), gamma/beta: [C].
// Per-CHANNEL stats over masked tokens (ddof=1), out = m ? g*(y-mean)/(std+eps)+b : y.

#define CCH   1024
#define RTOT  32768          // B*T
#define NBLK  296            // reduce blocks: 2 per SM * 148
#define G3    2048           // normalize blocks (trip count 16 per block)
#define EPSF  1e-4f

__device__ __align__(16) float g_psum[NBLK][CCH];
__device__ __align__(16) float g_psq [NBLK][CCH];
__device__ int   g_pcnt[NBLK];
__device__ __align__(16) float g_scale[CCH];
__device__ __align__(16) float g_shift[CCH];

// ---------- Pass 1: per-channel partial sums over masked rows ----------
__global__ __launch_bounds__(1024, 2)
void mn_reduce(const float* __restrict__ y, const int* __restrict__ mask) {
    const int c = threadIdx.x;       // channel, 0..1023
    const int p = blockIdx.x;        // partial slot, 0..NBLK-1
    float s = 0.0f, q = 0.0f;
    int cnt = 0;
    #pragma unroll 4
    for (int r = p; r < RTOT; r += NBLK) {
        const int m = __ldg(&mask[r]);
        if (m > 0) {
            const float v = __ldg(&y[r * CCH + c]);
            s += v;
            q = fmaf(v, v, q);
            cnt++;
        }
    }
    g_psum[p][c] = s;
    g_psq [p][c] = q;
    if (c == 0) g_pcnt[p] = cnt;
}

// ---------- Pass 2: fold partials -> scale/shift per channel ----------
__global__ __launch_bounds__(1024, 1)
void mn_stats(const float* __restrict__ gamma, const float* __restrict__ beta) {
    const int c = threadIdx.x;
    float s = 0.0f, q = 0.0f;
    int n = 0;
    #pragma unroll 8
    for (int p = 0; p < NBLK; p++) {
        s += g_psum[p][c];
        q += g_psq [p][c];
        n += g_pcnt[p];
    }
    const float nf   = (float)n;
    const float mean = s / nf;
    const float var  = (q - s * s / nf) / (nf - 1.0f);
    const float sd   = sqrtf(var);
    const float sc   = __ldg(&gamma[c]) / (sd + EPSF);
    g_scale[c] = sc;
    g_shift[c] = __ldg(&beta[c]) - mean * sc;  // out = fma(y, sc, shift)
}

// ---------- Pass 3: normalize (float4, fixed channel per thread) ----------
__global__ __launch_bounds__(256, 8)
void mn_norm(const float4* __restrict__ y4, const int* __restrict__ mask,
             float4* __restrict__ out4) {
    const int t = threadIdx.x;  // 0..255 -> channels 4t..4t+3
    const float4 sc = reinterpret_cast<const float4*>(g_scale)[t];
    const float4 sh = reinterpret_cast<const float4*>(g_shift)[t];
    #pragma unroll 4
    for (int r = blockIdx.x; r < RTOT; r += G3) {
        const int m = __ldg(&mask[r]);
        float4 v = __ldg(&y4[r * (CCH / 4) + t]);
        float4 o;
        if (m > 0) {
            o.x = fmaf(v.x, sc.x, sh.x);
            o.y = fmaf(v.y, sc.y, sh.y);
            o.z = fmaf(v.z, sc.z, sh.z);
            o.w = fmaf(v.w, sc.w, sh.w);
        } else {
            o = v;
        }
        out4[r * (CCH / 4) + t] = o;
    }
}

extern "C" void kernel_launch(void* const* d_in, const int* in_sizes, int n_in,
                              void* d_out, int out_size) {
    const float* y     = (const float*)d_in[0];
    const int*   mask  = (const int*)  d_in[1];
    const float* gamma = (const float*)d_in[2];
    const float* beta  = (const float*)d_in[3];
    float*       out   = (float*)d_out;

    mn_reduce<<<NBLK, 1024>>>(y, mask);
    mn_stats<<<1, 1024>>>(gamma, beta);
    mn_norm<<<G3, 256>>>((const float4*)y, mask, (float4*)out);
}

// round 2
// speedup vs baseline: 1.1810x; 1.1810x over previous
#include <cuda_runtime.h>
#include <math.h>

// MaskedNorm: B=8, T=4096, C=1024 fp32.
// Per-CHANNEL stats over masked tokens (ddof=1), out = m ? g*(y-mean)/(std+eps)+b : y.

#define CCH   1024
#define C4    (CCH / 4)      // 256 float4 per row
#define RTOT  32768          // B*T
#define NBLK  296            // reduce partial slots (2 per SM)
#define G3    512            // normalize blocks: 8192 row-groups / 512 = 16 iters exact
#define EPSF  1e-4f

__device__ __align__(16) float g_psum[NBLK][CCH];
__device__ __align__(16) float g_psq [NBLK][CCH];
__device__ int   g_pcnt[NBLK];
__device__ __align__(16) float g_scale[CCH];
__device__ __align__(16) float g_shift[CCH];

__device__ __forceinline__ void acc4(float4& s, float4& q, const float4 v) {
    s.x += v.x; s.y += v.y; s.z += v.z; s.w += v.w;
    q.x = fmaf(v.x, v.x, q.x);
    q.y = fmaf(v.y, v.y, q.y);
    q.z = fmaf(v.z, v.z, q.z);
    q.w = fmaf(v.w, v.w, q.w);
}

// ---------- Pass 1: per-channel partial sums over masked rows ----------
// 256 threads; thread t owns channels [4t, 4t+4). 4 rows per iteration,
// masks fetched as one int4 -> 4 independent guarded 16B loads (MLP=4).
__global__ __launch_bounds__(256, 8)
void mn_reduce(const float4* __restrict__ y4, const int4* __restrict__ mask4) {
    const int t = threadIdx.x;       // float4 channel slot
    const int p = blockIdx.x;        // partial slot
    float4 s = make_float4(0.f, 0.f, 0.f, 0.f);
    float4 q = make_float4(0.f, 0.f, 0.f, 0.f);
    int cnt = 0;

    for (int r = p * 4; r < RTOT; r += NBLK * 4) {
        const int4 mk = __ldg(&mask4[r >> 2]);
        if (mk.x > 0) { acc4(s, q, __ldcs(&y4[(r + 0) * C4 + t])); cnt++; }
        if (mk.y > 0) { acc4(s, q, __ldcs(&y4[(r + 1) * C4 + t])); cnt++; }
        if (mk.z > 0) { acc4(s, q, __ldcs(&y4[(r + 2) * C4 + t])); cnt++; }
        if (mk.w > 0) { acc4(s, q, __ldcs(&y4[(r + 3) * C4 + t])); cnt++; }
    }
    reinterpret_cast<float4*>(g_psum[p])[t] = s;
    reinterpret_cast<float4*>(g_psq [p])[t] = q;
    if (t == 0) g_pcnt[p] = cnt;
}

// ---------- Pass 2: fold partials -> scale/shift per channel ----------
__global__ __launch_bounds__(1024, 1)
void mn_stats(const float* __restrict__ gamma, const float* __restrict__ beta) {
    const int c = threadIdx.x;
    float s = 0.0f, q = 0.0f;
    int n = 0;
    #pragma unroll 8
    for (int p = 0; p < NBLK; p++) {
        s += g_psum[p][c];
        q += g_psq [p][c];
        n += g_pcnt[p];
    }
    const float nf   = (float)n;
    const float mean = s / nf;
    const float var  = (q - s * s / nf) / (nf - 1.0f);
    const float sd   = sqrtf(var);
    const float sc   = __ldg(&gamma[c]) / (sd + EPSF);
    g_scale[c] = sc;
    g_shift[c] = __ldg(&beta[c]) - mean * sc;  // out = fma(y, sc, shift)
}

// ---------- Pass 3: normalize (float4, 4 rows/iter, streaming) ----------
__global__ __launch_bounds__(256, 8)
void mn_norm(const float4* __restrict__ y4, const int4* __restrict__ mask4,
             float4* __restrict__ out4) {
    const int t = threadIdx.x;
    const float4 sc = reinterpret_cast<const float4*>(g_scale)[t];
    const float4 sh = reinterpret_cast<const float4*>(g_shift)[t];

    for (int r = blockIdx.x * 4; r < RTOT; r += G3 * 4) {
        const int4 mk = __ldg(&mask4[r >> 2]);
        float4 v0 = __ldcs(&y4[(r + 0) * C4 + t]);
        float4 v1 = __ldcs(&y4[(r + 1) * C4 + t]);
        float4 v2 = __ldcs(&y4[(r + 2) * C4 + t]);
        float4 v3 = __ldcs(&y4[(r + 3) * C4 + t]);
        float4 o0 = v0, o1 = v1, o2 = v2, o3 = v3;
        if (mk.x > 0) {
            o0.x = fmaf(v0.x, sc.x, sh.x); o0.y = fmaf(v0.y, sc.y, sh.y);
            o0.z = fmaf(v0.z, sc.z, sh.z); o0.w = fmaf(v0.w, sc.w, sh.w);
        }
        if (mk.y > 0) {
            o1.x = fmaf(v1.x, sc.x, sh.x); o1.y = fmaf(v1.y, sc.y, sh.y);
            o1.z = fmaf(v1.z, sc.z, sh.z); o1.w = fmaf(v1.w, sc.w, sh.w);
        }
        if (mk.z > 0) {
            o2.x = fmaf(v2.x, sc.x, sh.x); o2.y = fmaf(v2.y, sc.y, sh.y);
            o2.z = fmaf(v2.z, sc.z, sh.z); o2.w = fmaf(v2.w, sc.w, sh.w);
        }
        if (mk.w > 0) {
            o3.x = fmaf(v3.x, sc.x, sh.x); o3.y = fmaf(v3.y, sc.y, sh.y);
            o3.z = fmaf(v3.z, sc.z, sh.z); o3.w = fmaf(v3.w, sc.w, sh.w);
        }
        __stcs(&out4[(r + 0) * C4 + t], o0);
        __stcs(&out4[(r + 1) * C4 + t], o1);
        __stcs(&out4[(r + 2) * C4 + t], o2);
        __stcs(&out4[(r + 3) * C4 + t], o3);
    }
}

extern "C" void kernel_launch(void* const* d_in, const int* in_sizes, int n_in,
                              void* d_out, int out_size) {
    const float* y     = (const float*)d_in[0];
    const int*   mask  = (const int*)  d_in[1];
    const float* gamma = (const float*)d_in[2];
    const float* beta  = (const float*)d_in[3];
    float*       out   = (float*)d_out;

    mn_reduce<<<NBLK, 256>>>((const float4*)y, (const int4*)mask);
    mn_stats<<<1, 1024>>>(gamma, beta);
    mn_norm<<<G3, 256>>>((const float4*)y, (const int4*)mask, (float4*)out);
}

// round 3
// speedup vs baseline: 1.2602x; 1.0671x over previous
#include <cuda_runtime.h>
#include <math.h>

// MaskedNorm: B=8, T=4096, C=1024 fp32.
// Per-CHANNEL stats over masked tokens (ddof=1), out = m ? g*(y-mean)/(std+eps)+b : y.

#define CCH   1024
#define C4    (CCH / 4)      // 256 float4 per row
#define RTOT  32768          // B*T
#define NBLK  1184           // reduce partial slots: 8 blocks/SM * 148 SMs
#define G3    1184           // normalize blocks (full occupancy @256thr)
#define EPSF  1e-4f

__device__ __align__(16) float g_psum[NBLK][CCH];
__device__ __align__(16) float g_psq [NBLK][CCH];
__device__ int   g_pcnt[NBLK];
__device__ __align__(16) float g_scale[CCH];
__device__ __align__(16) float g_shift[CCH];

__device__ __forceinline__ void acc4(float4& s, float4& q, const float4 v) {
    s.x += v.x; s.y += v.y; s.z += v.z; s.w += v.w;
    q.x = fmaf(v.x, v.x, q.x);
    q.y = fmaf(v.y, v.y, q.y);
    q.z = fmaf(v.z, v.z, q.z);
    q.w = fmaf(v.w, v.w, q.w);
}

// ---------- Pass 1: per-channel partial sums over masked rows ----------
// 256 threads; thread t owns channels [4t, 4t+4). 4 rows per iteration,
// masks fetched as one int4 -> 4 independent guarded 16B loads.
__global__ __launch_bounds__(256, 8)
void mn_reduce(const float4* __restrict__ y4, const int4* __restrict__ mask4) {
    const int t = threadIdx.x;       // float4 channel slot
    const int p = blockIdx.x;        // partial slot
    float4 s = make_float4(0.f, 0.f, 0.f, 0.f);
    float4 q = make_float4(0.f, 0.f, 0.f, 0.f);
    int cnt = 0;

    for (int r = p * 4; r < RTOT; r += NBLK * 4) {
        const int4 mk = __ldg(&mask4[r >> 2]);
        if (mk.x > 0) { acc4(s, q, __ldcs(&y4[(r + 0) * C4 + t])); cnt++; }
        if (mk.y > 0) { acc4(s, q, __ldcs(&y4[(r + 1) * C4 + t])); cnt++; }
        if (mk.z > 0) { acc4(s, q, __ldcs(&y4[(r + 2) * C4 + t])); cnt++; }
        if (mk.w > 0) { acc4(s, q, __ldcs(&y4[(r + 3) * C4 + t])); cnt++; }
    }
    reinterpret_cast<float4*>(g_psum[p])[t] = s;
    reinterpret_cast<float4*>(g_psq [p])[t] = q;
    if (t == 0) g_pcnt[p] = cnt;
}

// ---------- Pass 2: fold partials -> scale/shift (parallel, coalesced) ----------
// 32 blocks x 256 threads. Block owns 32 channels (lanes); 8 warps stride
// over partial slots p with fully-coalesced 128B loads, then smem fold.
__global__ __launch_bounds__(256, 8)
void mn_stats(const float* __restrict__ gamma, const float* __restrict__ beta) {
    __shared__ float ssum[8][32];
    __shared__ float ssq [8][32];
    __shared__ int   sn;
    const int lane = threadIdx.x & 31;
    const int w    = threadIdx.x >> 5;
    const int c    = blockIdx.x * 32 + lane;

    float s = 0.0f, q = 0.0f;
    #pragma unroll 4
    for (int p = w; p < NBLK; p += 8) {
        s += g_psum[p][c];
        q += g_psq [p][c];
    }
    ssum[w][lane] = s;
    ssq [w][lane] = q;

    if (w == 0) {
        int n = 0;
        for (int p = lane; p < NBLK; p += 32) n += g_pcnt[p];
        #pragma unroll
        for (int o = 16; o; o >>= 1) n += __shfl_down_sync(0xffffffffu, n, o);
        if (lane == 0) sn = n;
    }
    __syncthreads();

    if (w == 0) {
        float S = 0.0f, Q = 0.0f;
        #pragma unroll
        for (int i = 0; i < 8; i++) { S += ssum[i][lane]; Q += ssq[i][lane]; }
        const float nf   = (float)sn;
        const float mean = S / nf;
        const float var  = (Q - S * S / nf) / (nf - 1.0f);
        const float sd   = sqrtf(var);
        const float sc   = __ldg(&gamma[c]) / (sd + EPSF);
        g_scale[c] = sc;
        g_shift[c] = __ldg(&beta[c]) - mean * sc;   // out = fma(y, sc, shift)
    }
}

// ---------- Pass 3: normalize (float4, 4 rows/iter, streaming) ----------
__global__ __launch_bounds__(256, 8)
void mn_norm(const float4* __restrict__ y4, const int4* __restrict__ mask4,
             float4* __restrict__ out4) {
    const int t = threadIdx.x;
    const float4 sc = reinterpret_cast<const float4*>(g_scale)[t];
    const float4 sh = reinterpret_cast<const float4*>(g_shift)[t];

    for (int r = blockIdx.x * 4; r < RTOT; r += G3 * 4) {
        const int4 mk = __ldg(&mask4[r >> 2]);
        float4 v0 = __ldcs(&y4[(r + 0) * C4 + t]);
        float4 v1 = __ldcs(&y4[(r + 1) * C4 + t]);
        float4 v2 = __ldcs(&y4[(r + 2) * C4 + t]);
        float4 v3 = __ldcs(&y4[(r + 3) * C4 + t]);
        float4 o0 = v0, o1 = v1, o2 = v2, o3 = v3;
        if (mk.x > 0) {
            o0.x = fmaf(v0.x, sc.x, sh.x); o0.y = fmaf(v0.y, sc.y, sh.y);
            o0.z = fmaf(v0.z, sc.z, sh.z); o0.w = fmaf(v0.w, sc.w, sh.w);
        }
        if (mk.y > 0) {
            o1.x = fmaf(v1.x, sc.x, sh.x); o1.y = fmaf(v1.y, sc.y, sh.y);
            o1.z = fmaf(v1.z, sc.z, sh.z); o1.w = fmaf(v1.w, sc.w, sh.w);
        }
        if (mk.z > 0) {
            o2.x = fmaf(v2.x, sc.x, sh.x); o2.y = fmaf(v2.y, sc.y, sh.y);
            o2.z = fmaf(v2.z, sc.z, sh.z); o2.w = fmaf(v2.w, sc.w, sh.w);
        }
        if (mk.w > 0) {
            o3.x = fmaf(v3.x, sc.x, sh.x); o3.y = fmaf(v3.y, sc.y, sh.y);
            o3.z = fmaf(v3.z, sc.z, sh.z); o3.w = fmaf(v3.w, sc.w, sh.w);
        }
        __stcs(&out4[(r + 0) * C4 + t], o0);
        __stcs(&out4[(r + 1) * C4 + t], o1);
        __stcs(&out4[(r + 2) * C4 + t], o2);
        __stcs(&out4[(r + 3) * C4 + t], o3);
    }
}

extern "C" void kernel_launch(void* const* d_in, const int* in_sizes, int n_in,
                              void* d_out, int out_size) {
    const float* y     = (const float*)d_in[0];
    const int*   mask  = (const int*)  d_in[1];
    const float* gamma = (const float*)d_in[2];
    const float* beta  = (const float*)d_in[3];
    float*       out   = (float*)d_out;

    mn_reduce<<<NBLK, 256>>>((const float4*)y, (const int4*)mask);
    mn_stats<<<32, 256>>>(gamma, beta);
    mn_norm<<<G3, 256>>>((const float4*)y, (const int4*)mask, (float4*)out);
}

// round 4
// speedup vs baseline: 1.5273x; 1.2119x over previous
#include <cuda_runtime.h>
#include <math.h>

// MaskedNorm: B=8, T=4096, C=1024 fp32.
// Per-CHANNEL stats over masked tokens (ddof=1), out = m ? g*(y-mean)/(std+eps)+b : y.

#define CCH   1024
#define C4    (CCH / 4)      // 256 float4 per row
#define RTOT  32768          // B*T
#define R4TOT (RTOT / 4)     // 8192 row-quads
#define NBLK  296            // reduce blocks: 2/SM x 148 SMs (1024 thr each)
#define G3    1184           // normalize blocks (8/SM @256thr)
#define EPSF  1e-4f

__device__ __align__(16) float g_psum[NBLK][CCH];
__device__ __align__(16) float g_psq [NBLK][CCH];
__device__ int   g_pcnt[NBLK];
__device__ __align__(16) float g_scale[CCH];
__device__ __align__(16) float g_shift[CCH];

__device__ __forceinline__ void acc4(float4& s, float4& q, const float4 v) {
    s.x += v.x; s.y += v.y; s.z += v.z; s.w += v.w;
    q.x = fmaf(v.x, v.x, q.x);
    q.y = fmaf(v.y, v.y, q.y);
    q.z = fmaf(v.z, v.z, q.z);
    q.w = fmaf(v.w, v.w, q.w);
}

// ---------- Pass 1: per-channel partial sums over masked rows ----------
// 1024 threads = 4 row-groups x 256 channel-threads. Group g covers row-quad
// (p*4+g) each iteration (one int4 mask load -> 4 guarded 16B y loads).
// Default-cached y loads so masked rows stay resident in L2 for pass 3.
__global__ __launch_bounds__(1024, 2)
void mn_reduce(const float4* __restrict__ y4, const int4* __restrict__ mask4) {
    __shared__ float4 ssum[4][256];
    __shared__ float4 ssq [4][256];
    __shared__ int    scnt[4];
    const int t = threadIdx.x & 255;   // channel slot (4 channels)
    const int g = threadIdx.x >> 8;    // row group 0..3
    const int p = blockIdx.x;

    float4 s = make_float4(0.f, 0.f, 0.f, 0.f);
    float4 q = make_float4(0.f, 0.f, 0.f, 0.f);
    int cnt = 0;

    for (int r4 = p * 4 + g; r4 < R4TOT; r4 += NBLK * 4) {
        const int  r  = r4 * 4;
        const int4 mk = __ldg(&mask4[r4]);
        if (mk.x > 0) { acc4(s, q, __ldg(&y4[(r + 0) * C4 + t])); cnt++; }
        if (mk.y > 0) { acc4(s, q, __ldg(&y4[(r + 1) * C4 + t])); cnt++; }
        if (mk.z > 0) { acc4(s, q, __ldg(&y4[(r + 2) * C4 + t])); cnt++; }
        if (mk.w > 0) { acc4(s, q, __ldg(&y4[(r + 3) * C4 + t])); cnt++; }
    }
    ssum[g][t] = s;
    ssq [g][t] = q;
    if (t == 0) scnt[g] = cnt;   // cnt identical across t within a group
    __syncthreads();

    if (g == 0) {
        float4 S = ssum[0][t], Q = ssq[0][t];
        #pragma unroll
        for (int i = 1; i < 4; i++) {
            const float4 a = ssum[i][t], b = ssq[i][t];
            S.x += a.x; S.y += a.y; S.z += a.z; S.w += a.w;
            Q.x += b.x; Q.y += b.y; Q.z += b.z; Q.w += b.w;
        }
        reinterpret_cast<float4*>(g_psum[p])[t] = S;
        reinterpret_cast<float4*>(g_psq [p])[t] = Q;
        if (t == 0) g_pcnt[p] = scnt[0] + scnt[1] + scnt[2] + scnt[3];
    }
}

// ---------- Pass 2: fold partials -> scale/shift (parallel, coalesced) ----------
// 32 blocks x 256 threads. Block owns 32 channels (lanes); 8 warps stride
// over partial slots with coalesced 128B loads, then smem fold.
__global__ __launch_bounds__(256, 8)
void mn_stats(const float* __restrict__ gamma, const float* __restrict__ beta) {
    __shared__ float ssum[8][32];
    __shared__ float ssq [8][32];
    __shared__ int   sn;
    const int lane = threadIdx.x & 31;
    const int w    = threadIdx.x >> 5;
    const int c    = blockIdx.x * 32 + lane;

    float s = 0.0f, q = 0.0f;
    #pragma unroll 4
    for (int p = w; p < NBLK; p += 8) {
        s += g_psum[p][c];
        q += g_psq [p][c];
    }
    ssum[w][lane] = s;
    ssq [w][lane] = q;

    if (w == 0) {
        int n = 0;
        for (int p = lane; p < NBLK; p += 32) n += g_pcnt[p];
        #pragma unroll
        for (int o = 16; o; o >>= 1) n += __shfl_down_sync(0xffffffffu, n, o);
        if (lane == 0) sn = n;
    }
    __syncthreads();

    if (w == 0) {
        float S = 0.0f, Q = 0.0f;
        #pragma unroll
        for (int i = 0; i < 8; i++) { S += ssum[i][lane]; Q += ssq[i][lane]; }
        const float nf   = (float)sn;
        const float mean = S / nf;
        const float var  = (Q - S * S / nf) / (nf - 1.0f);
        const float sd   = sqrtf(var);
        const float sc   = __ldg(&gamma[c]) / (sd + EPSF);
        g_scale[c] = sc;
        g_shift[c] = __ldg(&beta[c]) - mean * sc;   // out = fma(y, sc, shift)
    }
}

// ---------- Pass 3: normalize (float4, 4 rows/iter) ----------
// Default-cached loads (masked rows hit L2 from pass 1); streaming stores.
__global__ __launch_bounds__(256, 8)
void mn_norm(const float4* __restrict__ y4, const int4* __restrict__ mask4,
             float4* __restrict__ out4) {
    const int t = threadIdx.x;
    const float4 sc = reinterpret_cast<const float4*>(g_scale)[t];
    const float4 sh = reinterpret_cast<const float4*>(g_shift)[t];

    for (int r = blockIdx.x * 4; r < RTOT; r += G3 * 4) {
        const int4 mk = __ldg(&mask4[r >> 2]);
        float4 v0 = __ldg(&y4[(r + 0) * C4 + t]);
        float4 v1 = __ldg(&y4[(r + 1) * C4 + t]);
        float4 v2 = __ldg(&y4[(r + 2) * C4 + t]);
        float4 v3 = __ldg(&y4[(r + 3) * C4 + t]);
        float4 o0 = v0, o1 = v1, o2 = v2, o3 = v3;
        if (mk.x > 0) {
            o0.x = fmaf(v0.x, sc.x, sh.x); o0.y = fmaf(v0.y, sc.y, sh.y);
            o0.z = fmaf(v0.z, sc.z, sh.z); o0.w = fmaf(v0.w, sc.w, sh.w);
        }
        if (mk.y > 0) {
            o1.x = fmaf(v1.x, sc.x, sh.x); o1.y = fmaf(v1.y, sc.y, sh.y);
            o1.z = fmaf(v1.z, sc.z, sh.z); o1.w = fmaf(v1.w, sc.w, sh.w);
        }
        if (mk.z > 0) {
            o2.x = fmaf(v2.x, sc.x, sh.x); o2.y = fmaf(v2.y, sc.y, sh.y);
            o2.z = fmaf(v2.z, sc.z, sh.z); o2.w = fmaf(v2.w, sc.w, sh.w);
        }
        if (mk.w > 0) {
            o3.x = fmaf(v3.x, sc.x, sh.x); o3.y = fmaf(v3.y, sc.y, sh.y);
            o3.z = fmaf(v3.z, sc.z, sh.z); o3.w = fmaf(v3.w, sc.w, sh.w);
        }
        __stcs(&out4[(r + 0) * C4 + t], o0);
        __stcs(&out4[(r + 1) * C4 + t], o1);
        __stcs(&out4[(r + 2) * C4 + t], o2);
        __stcs(&out4[(r + 3) * C4 + t], o3);
    }
}

extern "C" void kernel_launch(void* const* d_in, const int* in_sizes, int n_in,
                              void* d_out, int out_size) {
    const float* y     = (const float*)d_in[0];
    const int*   mask  = (const int*)  d_in[1];
    const float* gamma = (const float*)d_in[2];
    const float* beta  = (const float*)d_in[3];
    float*       out   = (float*)d_out;

    mn_reduce<<<NBLK, 1024>>>((const float4*)y, (const int4*)mask);
    mn_stats<<<32, 256>>>(gamma, beta);
    mn_norm<<<G3, 256>>>((const float4*)y, (const int4*)mask, (float4*)out);
}

// round 5
// speedup vs baseline: 1.5280x; 1.0005x over previous
#include <cuda_runtime.h>
#include <math.h>

// MaskedNorm: B=8, T=4096, C=1024 fp32.
// Per-CHANNEL stats over masked tokens (ddof=1), out = m ? g*(y-mean)/(std+eps)+b : y.

#define CCH   1024
#define C4    (CCH / 4)      // 256 float4 per row
#define RTOT  32768          // B*T
#define R4TOT (RTOT / 4)     // 8192 row-quads
#define R8TOT (RTOT / 8)     // 4096 row-octets
#define NBLK  296            // reduce blocks: 2/SM x 148 SMs (1024 thr each)
#define G3    1024           // normalize blocks: 4096/1024 = 4 iters exact
#define EPSF  1e-4f

__device__ __align__(16) float g_psum[NBLK][CCH];
__device__ __align__(16) float g_psq [NBLK][CCH];
__device__ int   g_pcnt[NBLK];
__device__ __align__(16) float g_scale[CCH];
__device__ __align__(16) float g_shift[CCH];

__device__ __forceinline__ void acc4(float4& s, float4& q, const float4 v) {
    s.x += v.x; s.y += v.y; s.z += v.z; s.w += v.w;
    q.x = fmaf(v.x, v.x, q.x);
    q.y = fmaf(v.y, v.y, q.y);
    q.z = fmaf(v.z, v.z, q.z);
    q.w = fmaf(v.w, v.w, q.w);
}

// ---------- Pass 1: per-channel partial sums over masked rows ----------
// 1024 threads = 4 row-groups x 256 channel-threads. Default-cached y loads
// so masked rows stay resident in L2 for pass 3.
__global__ __launch_bounds__(1024, 2)
void mn_reduce(const float4* __restrict__ y4, const int4* __restrict__ mask4) {
    __shared__ float4 ssum[4][256];
    __shared__ float4 ssq [4][256];
    __shared__ int    scnt[4];
    const int t = threadIdx.x & 255;   // channel slot (4 channels)
    const int g = threadIdx.x >> 8;    // row group 0..3
    const int p = blockIdx.x;

    float4 s = make_float4(0.f, 0.f, 0.f, 0.f);
    float4 q = make_float4(0.f, 0.f, 0.f, 0.f);
    int cnt = 0;

    for (int r4 = p * 4 + g; r4 < R4TOT; r4 += NBLK * 4) {
        const int  r  = r4 * 4;
        const int4 mk = __ldg(&mask4[r4]);
        if (mk.x > 0) { acc4(s, q, __ldg(&y4[(r + 0) * C4 + t])); cnt++; }
        if (mk.y > 0) { acc4(s, q, __ldg(&y4[(r + 1) * C4 + t])); cnt++; }
        if (mk.z > 0) { acc4(s, q, __ldg(&y4[(r + 2) * C4 + t])); cnt++; }
        if (mk.w > 0) { acc4(s, q, __ldg(&y4[(r + 3) * C4 + t])); cnt++; }
    }
    ssum[g][t] = s;
    ssq [g][t] = q;
    if (t == 0) scnt[g] = cnt;   // cnt identical across t within a group
    __syncthreads();

    if (g == 0) {
        float4 S = ssum[0][t], Q = ssq[0][t];
        #pragma unroll
        for (int i = 1; i < 4; i++) {
            const float4 a = ssum[i][t], b = ssq[i][t];
            S.x += a.x; S.y += a.y; S.z += a.z; S.w += a.w;
            Q.x += b.x; Q.y += b.y; Q.z += b.z; Q.w += b.w;
        }
        reinterpret_cast<float4*>(g_psum[p])[t] = S;
        reinterpret_cast<float4*>(g_psq [p])[t] = Q;
        if (t == 0) g_pcnt[p] = scnt[0] + scnt[1] + scnt[2] + scnt[3];
    }
}

// ---------- Pass 2: fold partials -> scale/shift (parallel, coalesced) ----------
__global__ __launch_bounds__(256, 8)
void mn_stats(const float* __restrict__ gamma, const float* __restrict__ beta) {
    __shared__ float ssum[8][32];
    __shared__ float ssq [8][32];
    __shared__ int   sn;
    const int lane = threadIdx.x & 31;
    const int w    = threadIdx.x >> 5;
    const int c    = blockIdx.x * 32 + lane;

    float s = 0.0f, q = 0.0f;
    #pragma unroll 4
    for (int p = w; p < NBLK; p += 8) {
        s += g_psum[p][c];
        q += g_psq [p][c];
    }
    ssum[w][lane] = s;
    ssq [w][lane] = q;

    if (w == 0) {
        int n = 0;
        for (int p = lane; p < NBLK; p += 32) n += g_pcnt[p];
        #pragma unroll
        for (int o = 16; o; o >>= 1) n += __shfl_down_sync(0xffffffffu, n, o);
        if (lane == 0) sn = n;
    }
    __syncthreads();

    if (w == 0) {
        float S = 0.0f, Q = 0.0f;
        #pragma unroll
        for (int i = 0; i < 8; i++) { S += ssum[i][lane]; Q += ssq[i][lane]; }
        const float nf   = (float)sn;
        const float mean = S / nf;
        const float var  = (Q - S * S / nf) / (nf - 1.0f);
        const float sd   = sqrtf(var);
        const float sc   = __ldg(&gamma[c]) / (sd + EPSF);
        g_scale[c] = sc;
        g_shift[c] = __ldg(&beta[c]) - mean * sc;   // out = fma(y, sc, shift)
    }
}

// ---------- Pass 3: normalize (float4, 8 rows/iter, deep MLP) ----------
// 8 independent 16B loads batched per iteration; masked rows hit L2 from
// pass 1; streaming stores. Grid 1024 -> exactly 4 octets per block.
__global__ __launch_bounds__(256, 8)
void mn_norm(const float4* __restrict__ y4, const int4* __restrict__ mask4,
             float4* __restrict__ out4) {
    const int t = threadIdx.x;
    const float4 sc = reinterpret_cast<const float4*>(g_scale)[t];
    const float4 sh = reinterpret_cast<const float4*>(g_shift)[t];

    #pragma unroll 1
    for (int r8 = blockIdx.x; r8 < R8TOT; r8 += G3) {
        const int r = r8 * 8;
        const int4 ma = __ldg(&mask4[r8 * 2 + 0]);
        const int4 mb = __ldg(&mask4[r8 * 2 + 1]);
        float4 v0 = __ldg(&y4[(r + 0) * C4 + t]);
        float4 v1 = __ldg(&y4[(r + 1) * C4 + t]);
        float4 v2 = __ldg(&y4[(r + 2) * C4 + t]);
        float4 v3 = __ldg(&y4[(r + 3) * C4 + t]);
        float4 v4 = __ldg(&y4[(r + 4) * C4 + t]);
        float4 v5 = __ldg(&y4[(r + 5) * C4 + t]);
        float4 v6 = __ldg(&y4[(r + 6) * C4 + t]);
        float4 v7 = __ldg(&y4[(r + 7) * C4 + t]);

        if (ma.x > 0) { v0.x = fmaf(v0.x, sc.x, sh.x); v0.y = fmaf(v0.y, sc.y, sh.y);
                        v0.z = fmaf(v0.z, sc.z, sh.z); v0.w = fmaf(v0.w, sc.w, sh.w); }
        __stcs(&out4[(r + 0) * C4 + t], v0);
        if (ma.y > 0) { v1.x = fmaf(v1.x, sc.x, sh.x); v1.y = fmaf(v1.y, sc.y, sh.y);
                        v1.z = fmaf(v1.z, sc.z, sh.z); v1.w = fmaf(v1.w, sc.w, sh.w); }
        __stcs(&out4[(r + 1) * C4 + t], v1);
        if (ma.z > 0) { v2.x = fmaf(v2.x, sc.x, sh.x); v2.y = fmaf(v2.y, sc.y, sh.y);
                        v2.z = fmaf(v2.z, sc.z, sh.z); v2.w = fmaf(v2.w, sc.w, sh.w); }
        __stcs(&out4[(r + 2) * C4 + t], v2);
        if (ma.w > 0) { v3.x = fmaf(v3.x, sc.x, sh.x); v3.y = fmaf(v3.y, sc.y, sh.y);
                        v3.z = fmaf(v3.z, sc.z, sh.z); v3.w = fmaf(v3.w, sc.w, sh.w); }
        __stcs(&out4[(r + 3) * C4 + t], v3);
        if (mb.x > 0) { v4.x = fmaf(v4.x, sc.x, sh.x); v4.y = fmaf(v4.y, sc.y, sh.y);
                        v4.z = fmaf(v4.z, sc.z, sh.z); v4.w = fmaf(v4.w, sc.w, sh.w); }
        __stcs(&out4[(r + 4) * C4 + t], v4);
        if (mb.y > 0) { v5.x = fmaf(v5.x, sc.x, sh.x); v5.y = fmaf(v5.y, sc.y, sh.y);
                        v5.z = fmaf(v5.z, sc.z, sh.z); v5.w = fmaf(v5.w, sc.w, sh.w); }
        __stcs(&out4[(r + 5) * C4 + t], v5);
        if (mb.z > 0) { v6.x = fmaf(v6.x, sc.x, sh.x); v6.y = fmaf(v6.y, sc.y, sh.y);
                        v6.z = fmaf(v6.z, sc.z, sh.z); v6.w = fmaf(v6.w, sc.w, sh.w); }
        __stcs(&out4[(r + 6) * C4 + t], v6);
        if (mb.w > 0) { v7.x = fmaf(v7.x, sc.x, sh.x); v7.y = fmaf(v7.y, sc.y, sh.y);
                        v7.z = fmaf(v7.z, sc.z, sh.z); v7.w = fmaf(v7.w, sc.w, sh.w); }
        __stcs(&out4[(r + 7) * C4 + t], v7);
    }
}

extern "C" void kernel_launch(void* const* d_in, const int* in_sizes, int n_in,
                              void* d_out, int out_size) {
    const float* y     = (const float*)d_in[0];
    const int*   mask  = (const int*)  d_in[1];
    const float* gamma = (const float*)d_in[2];
    const float* beta  = (const float*)d_in[3];
    float*       out   = (float*)d_out;

    mn_reduce<<<NBLK, 1024>>>((const float4*)y, (const int4*)mask);
    mn_stats<<<32, 256>>>(gamma, beta);
    mn_norm<<<G3, 256>>>((const float4*)y, (const int4*)mask, (float4*)out);
}